// round 2
// baseline (speedup 1.0000x reference)
#include <cuda_runtime.h>
#include <cuda_bf16.h>

// PCEN: M_t = (1-s) M_{t-1} + s x_t  (per [b,f] row along T),
// out = (x / (EPS + M)^alpha + bias)^power - bias^power
//
// One CTA per row of T=2048. 256 threads x 8 contiguous elems.
// Linear-recurrence scan: thread-local recurrence from 0, then warp
// shuffle scan with constant decay factors, then cross-warp smem scan.

#define T_LEN 2048
#define NTHREADS 256
#define PER_THREAD 8
#define NWARPS (NTHREADS / 32)

__device__ __forceinline__ float fast_lg2(float x) {
    float r;
    asm("lg2.approx.f32 %0, %1;" : "=f"(r) : "f"(x));
    return r;
}
__device__ __forceinline__ float fast_ex2(float x) {
    float r;
    asm("ex2.approx.f32 %0, %1;" : "=f"(r) : "f"(x));
    return r;
}

__global__ __launch_bounds__(NTHREADS)
void pcen_kernel(const float* __restrict__ x,
                 const float* __restrict__ alpha_p,
                 const float* __restrict__ power_p,
                 const float* __restrict__ bias_p,
                 float* __restrict__ out)
{
    const float s  = 0.015f;
    const float c1 = 0.985f;      // 1 - s
    const float EPSv = 1e-9f;

    const int tid  = threadIdx.x;
    const int lane = tid & 31;
    const int warp = tid >> 5;

    const size_t base = (size_t)blockIdx.x * T_LEN;
    const float4* xin = (const float4*)(x + base);

    // Coalesced load of 8 contiguous elements per thread.
    float4 xa = xin[tid * 2];
    float4 xb = xin[tid * 2 + 1];
    float xv[PER_THREAD] = {xa.x, xa.y, xa.z, xa.w, xb.x, xb.y, xb.z, xb.w};

    // Thread-local recurrence from zero initial state.
    float b = 0.f;
    #pragma unroll
    for (int i = 0; i < PER_THREAD; i++)
        b = fmaf(c1, b, s * xv[i]);

    // Decay factor for one 8-element segment and its powers.
    const float c2 = c1 * c1;
    const float c4 = c2 * c2;
    const float f1 = c4 * c4;        // c1^8   (= A8)
    const float f2 = f1 * f1;        // A8^2
    const float f4 = f2 * f2;        // A8^4
    const float f8 = f4 * f4;        // A8^8
    const float f16 = f8 * f8;       // A8^16
    const float f32 = f16 * f16;     // A8^32  (per-warp decay)

    // Inclusive Kogge-Stone scan within warp: v_t = v_{t-d} * A8^d + v_t
    float v = b;
    float u;
    u = __shfl_up_sync(0xffffffffu, v, 1);  if (lane >= 1)  v = fmaf(u, f1,  v);
    u = __shfl_up_sync(0xffffffffu, v, 2);  if (lane >= 2)  v = fmaf(u, f2,  v);
    u = __shfl_up_sync(0xffffffffu, v, 4);  if (lane >= 4)  v = fmaf(u, f4,  v);
    u = __shfl_up_sync(0xffffffffu, v, 8);  if (lane >= 8)  v = fmaf(u, f8,  v);
    u = __shfl_up_sync(0xffffffffu, v, 16); if (lane >= 16) v = fmaf(u, f16, v);

    __shared__ float sW[NWARPS];   // inclusive warp totals
    __shared__ float sE[NWARPS];   // exclusive carry entering each warp
    if (lane == 31) sW[warp] = v;
    __syncthreads();
    if (tid == 0) {
        float c = 0.f;
        #pragma unroll
        for (int w = 0; w < NWARPS; w++) {
            sE[w] = c;
            c = fmaf(c, f32, sW[w]);
        }
    }
    __syncthreads();

    // Carry entering this thread's segment:
    //   m_in = warp_carry * A8^lane + inclusive_scan(lane-1)
    float prev = __shfl_up_sync(0xffffffffu, v, 1);
    if (lane == 0) prev = 0.f;

    // A8^lane by exact binary exponentiation (no MUFU).
    float p = 1.f;
    if (lane & 1)  p *= f1;
    if (lane & 2)  p *= f2;
    if (lane & 4)  p *= f4;
    if (lane & 8)  p *= f8;
    if (lane & 16) p *= f16;

    float m = fmaf(sE[warp], p, prev);

    // Scalars (broadcast loads).
    const float alpha = __ldg(alpha_p);
    const float power = __ldg(power_p);
    const float bias  = __ldg(bias_p);
    const float nalpha = -alpha;
    const float bp = fast_ex2(power * fast_lg2(bias));   // bias^power

    // Recompute exact recurrence for this segment and apply PCEN pointwise.
    float o[PER_THREAD];
    #pragma unroll
    for (int i = 0; i < PER_THREAD; i++) {
        m = fmaf(c1, m, s * xv[i]);
        float inv = fast_ex2(nalpha * fast_lg2(EPSv + m));  // (EPS+M)^(-alpha)
        float z = fmaf(xv[i], inv, bias);
        o[i] = fast_ex2(power * fast_lg2(z)) - bp;
    }

    float4* oout = (float4*)(out + base);
    oout[tid * 2]     = make_float4(o[0], o[1], o[2], o[3]);
    oout[tid * 2 + 1] = make_float4(o[4], o[5], o[6], o[7]);
}

extern "C" void kernel_launch(void* const* d_in, const int* in_sizes, int n_in,
                              void* d_out, int out_size)
{
    const float* x     = (const float*)d_in[0];
    const float* alpha = (const float*)d_in[1];
    const float* power = (const float*)d_in[2];
    const float* bias  = (const float*)d_in[3];
    float* out = (float*)d_out;

    int rows = in_sizes[0] / T_LEN;   // B*F = 16384
    pcen_kernel<<<rows, NTHREADS>>>(x, alpha, power, bias, out);
}